// round 16
// baseline (speedup 1.0000x reference)
#include <cuda_runtime.h>
#include <math.h>
#include <stdint.h>

// Problem dims
#define BB 32
#define TT 512
#define II 128
#define HH 512
#define OO 128
#define HB (HH * BB)   // 16384 floats per timestep slab

// ---------------- device scratch (no allocs allowed) ----------------
__device__ float    g_pre [TT * HH * BB];          // [T][H][B] pre0
__device__ float    g_h1  [(TT + 1) * HH * BB];    // h1 traj, slot-shifted: h1[t] at slot t+1, slot0 = 0
__device__ float    g_h2  [(TT + 1) * HH * BB];    // h2 traj, slot-shifted
__device__ float    g_tmp [TT * OO * BB];          // [T][O][B] fc pre-transpose
__device__ unsigned g_counters[1024];              // per-fused-step barrier counters (513 used)

// dynamic smem: 8192 float4 (two h slabs, 128KB) + 2*32*132 floats (partials, 33KB)
#define DSMEM_BYTES (131072 + 2 * 32 * 132 * 4)

// ---------------- init: zero counters + zero slot0 each replay ----------------
__global__ void init_kernel(unsigned* counters, float* h1, float* h2) {
    int i = blockIdx.x * blockDim.x + threadIdx.x;
    int stride = gridDim.x * blockDim.x;
    for (int e = i; e < 1024; e += stride) counters[e] = 0u;
    for (int e = i; e < HB; e += stride) { h1[e] = 0.0f; h2[e] = 0.0f; }
}

// ---------------- fp32 GEMM: C[t][j][b] = bias(j) + sum_k A(t,k,b)*W[j][k] ----------------
// grid: (N/128, T/2), block: 256. Tile 128j x 64n, microtile 8j x 4n. (R4-proven)
__global__ void __launch_bounds__(256)
gemm_pre_kernel(const float* __restrict__ A, const float* __restrict__ W,
                const float* __restrict__ bias1, const float* __restrict__ bias2,
                float* __restrict__ C,
                int K, long sAt, long sAk, long sAb, int N)
{
    __shared__ float Ws[32][132];  // [k][j] padded (128 j)
    __shared__ float As[32][68];   // [k][n] padded (64 n)

    const int t0  = blockIdx.y * 2;
    const int j0  = blockIdx.x * 128;
    const int tid = threadIdx.x;
    const int jg  = tid >> 4;      // 0..15 (8 j each)
    const int ng  = tid & 15;      // 0..15 (4 n each)

    float acc[8][4];
#pragma unroll
    for (int a = 0; a < 8; a++)
#pragma unroll
        for (int b = 0; b < 4; b++) acc[a][b] = 0.0f;

    for (int kt = 0; kt < K; kt += 32) {
        __syncthreads();
        {
            const int rowb = tid >> 3;
            const int k4   = (tid & 7) * 4;
#pragma unroll
            for (int i = 0; i < 4; i++) {
                const int row = i * 32 + rowb;
                float4 v = *(const float4*)&W[(size_t)(j0 + row) * K + kt + k4];
                Ws[k4 + 0][row] = v.x;
                Ws[k4 + 1][row] = v.y;
                Ws[k4 + 2][row] = v.z;
                Ws[k4 + 3][row] = v.w;
            }
        }
        if (sAb == 1) {   // b-contiguous (trajectory layout [t][k][b])
#pragma unroll
            for (int i = 0; i < 2; i++) {
                int f = tid + i * 256;
                int k  = f >> 4;
                int nq = (f & 15) * 4;
                int tloc = nq >> 5, b4 = nq & 31;
                float4 v = *(const float4*)&A[(size_t)(t0 + tloc) * sAt +
                                              (size_t)(kt + k) * sAk + b4];
                *(float4*)&As[k][nq] = v;
            }
        } else {          // k-contiguous (inputs layout [b][t][i])
#pragma unroll
            for (int i = 0; i < 2; i++) {
                int f = tid + i * 256;
                int n  = f >> 3;
                int kq = (f & 7) * 4;
                int tloc = n >> 5, b = n & 31;
                float4 v = *(const float4*)&A[(size_t)b * sAb +
                                              (size_t)(t0 + tloc) * sAt + kt + kq];
                As[kq + 0][n] = v.x;
                As[kq + 1][n] = v.y;
                As[kq + 2][n] = v.z;
                As[kq + 3][n] = v.w;
            }
        }
        __syncthreads();
#pragma unroll
        for (int k = 0; k < 32; k++) {
            const float4 w0 = *(const float4*)&Ws[k][jg * 8];
            const float4 w1 = *(const float4*)&Ws[k][jg * 8 + 4];
            const float4 a  = *(const float4*)&As[k][ng * 4];
            acc[0][0] += w0.x * a.x; acc[0][1] += w0.x * a.y; acc[0][2] += w0.x * a.z; acc[0][3] += w0.x * a.w;
            acc[1][0] += w0.y * a.x; acc[1][1] += w0.y * a.y; acc[1][2] += w0.y * a.z; acc[1][3] += w0.y * a.w;
            acc[2][0] += w0.z * a.x; acc[2][1] += w0.z * a.y; acc[2][2] += w0.z * a.z; acc[2][3] += w0.z * a.w;
            acc[3][0] += w0.w * a.x; acc[3][1] += w0.w * a.y; acc[3][2] += w0.w * a.z; acc[3][3] += w0.w * a.w;
            acc[4][0] += w1.x * a.x; acc[4][1] += w1.x * a.y; acc[4][2] += w1.x * a.z; acc[4][3] += w1.x * a.w;
            acc[5][0] += w1.y * a.x; acc[5][1] += w1.y * a.y; acc[5][2] += w1.y * a.z; acc[5][3] += w1.y * a.w;
            acc[6][0] += w1.z * a.x; acc[6][1] += w1.z * a.y; acc[6][2] += w1.z * a.z; acc[6][3] += w1.z * a.w;
            acc[7][0] += w1.w * a.x; acc[7][1] += w1.w * a.y; acc[7][2] += w1.w * a.z; acc[7][3] += w1.w * a.w;
        }
    }

    const int tloc = ng >> 3;
    const int b4   = (ng & 7) * 4;
    float* Crow = &C[(size_t)(t0 + tloc) * N * BB + b4];
#pragma unroll
    for (int ji = 0; ji < 8; ji++) {
        int j = j0 + jg * 8 + ji;
        float bb = bias1 ? bias1[j] : 0.0f;
        if (bias2) bb += bias2[j];
        float4 o = make_float4(acc[ji][0] + bb, acc[ji][1] + bb, acc[ji][2] + bb, acc[ji][3] + bb);
        *(float4*)&Crow[(size_t)j * BB] = o;
    }
}

// ---------------- cp.async helpers ----------------
__device__ __forceinline__ void cpasync16(uint32_t saddr, const void* gaddr) {
    asm volatile("cp.async.cg.shared.global [%0], [%1], 16;" :: "r"(saddr), "l"(gaddr));
}
__device__ __forceinline__ void cpasync_commit() {
    asm volatile("cp.async.commit_group;" ::: "memory");
}
template <int N>
__device__ __forceinline__ void cpasync_wait_group() {
    asm volatile("cp.async.wait_group %0;" :: "n"(N) : "memory");
}

// ---------------- fused two-layer wavefront recurrence (smem-staged) ----------------
// grid: 128 CTAs, block: 128 threads, ~161KB dynamic smem (two h slabs + partials).
// Fused step s: stage h1[s-1] and h2[s-2] slabs via cp.async (4 commit groups,
// pipelined against the 3 GEMM slices), compute h1[s] = tanh(pre0 + W_hh0 h1)
// and h2[s-1] = tanh(bias1 + W_ih1 h1 + W_hh1 h2). 513 barriers vs 1024.
// Barrier = R6-proven flat pattern.
__global__ void __launch_bounds__(128)
fused_rnn_kernel(const float* __restrict__ pre,
                 float* __restrict__ h1traj, float* __restrict__ h2traj,
                 const float* __restrict__ Whh0,
                 const float* __restrict__ Wih1, const float* __restrict__ Whh1,
                 const float* __restrict__ b_ih1, const float* __restrict__ b_hh1,
                 unsigned* counters)
{
    extern __shared__ float4 hs[];     // [0:4096) h1 slab, [4096:8192) h2 slab (swizzled), then ps0/ps1
    __shared__ float Wt0 [16][32][4];  // W_hh0 slice  8KB   (k = kk*32 + kseg)
    __shared__ float Wt1i[16][32][4];  // W_ih1 slice  8KB
    __shared__ float Wt1h[16][32][4];  // W_hh1 slice  8KB

    const int tid  = threadIdx.x;
    const int j0   = blockIdx.x * 4;
    const int bg   = tid & 3;
    const int kseg = tid >> 2;         // 0..31
    const uint32_t hs_base = (uint32_t)__cvta_generic_to_shared(hs);
    float4* const hs1 = hs;
    float4* const hs2 = hs + 4096;
    float* const ps0 = (float*)(hs + 8192);        // [32][132]
    float* const ps1 = ps0 + 32 * 132;             // [32][132]

    // preload W slices with interleaved k map: Wt[kk][ks][jj] = W[(j0+jj)*H + kk*32 + ks]
    for (int e = tid; e < 2048; e += 128) {
        int jj = e & 3;
        int ks = (e >> 2) & 31;
        int kk = e >> 7;
        size_t widx = (size_t)(j0 + jj) * HH + kk * 32 + ks;
        Wt0 [kk][ks][jj] = Whh0[widx];
        Wt1i[kk][ks][jj] = Wih1[widx];
        Wt1h[kk][ks][jj] = Whh1[widx];
    }
    __syncthreads();

    const int out_b  = tid >> 2;
    const int out_jj = tid & 3;
    const int jdx    = j0 + out_jj;
    const size_t pre_off = (size_t)jdx * BB + out_b;
    const float bias1v = b_ih1[jdx] + b_hh1[jdx];

    for (int s = 0; s <= TT; s++) {
        const bool l0 = (s < TT);                    // layer0 computes h1[s]
        const bool l1 = (s >= 1);                    // layer1 computes h2[s-1]
        const int  tp = l0 ? s : (TT - 1);           // clamped pre0 step
        const int  h2slot = l1 ? (s - 1) : 0;        // h2[s-2] slot (slot0 = zeros)

        const float4* g1 = (const float4*)(h1traj + (size_t)s * HB);
        const float4* g2 = (const float4*)(h2traj + (size_t)h2slot * HB);

        // ---- issue staging: 4 commit groups (h1 A, h1 B, h2 A, h2 B) ----
#pragma unroll
        for (int it = 0; it < 16; it++) {
            int u = tid + it * 128;
            int k = u >> 3, c = u & 7;
            int su = (k << 3) | (c ^ (k & 7));
            cpasync16(hs_base + su * 16, g1 + u);
        }
        cpasync_commit();
#pragma unroll
        for (int it = 16; it < 32; it++) {
            int u = tid + it * 128;
            int k = u >> 3, c = u & 7;
            int su = (k << 3) | (c ^ (k & 7));
            cpasync16(hs_base + su * 16, g1 + u);
        }
        cpasync_commit();
#pragma unroll
        for (int it = 0; it < 16; it++) {
            int u = tid + it * 128;
            int k = u >> 3, c = u & 7;
            int su = (k << 3) | (c ^ (k & 7));
            cpasync16(hs_base + 65536 + su * 16, g2 + u);
        }
        cpasync_commit();
#pragma unroll
        for (int it = 16; it < 32; it++) {
            int u = tid + it * 128;
            int k = u >> 3, c = u & 7;
            int su = (k << 3) | (c ^ (k & 7));
            cpasync16(hs_base + 65536 + su * 16, g2 + u);
        }
        cpasync_commit();

        const float preval = __ldcg(pre + (size_t)tp * HB + pre_off);

        float acc0[8][4], acc1[8][4];
#pragma unroll
        for (int a = 0; a < 8; a++)
#pragma unroll
            for (int b = 0; b < 4; b++) { acc0[a][b] = 0.0f; acc1[a][b] = 0.0f; }

        const int eb = bg * 2;   // base unit col pair for this thread's 8 b

        // ---- h1 half A: kk 0..7 -> acc0 (Whh0) and acc1 (Wih1) ----
        cpasync_wait_group<3>();
        __syncthreads();
#pragma unroll
        for (int kk = 0; kk < 8; kk++) {
            const int k = kk * 32 + kseg;
            const int e = eb ^ (k & 7);
            const float4 hA = hs1[(k << 3) | e];
            const float4 hB = hs1[(k << 3) | (e ^ 1)];
            const float4 w0 = *(const float4*)&Wt0 [kk][kseg][0];
            const float4 wi = *(const float4*)&Wt1i[kk][kseg][0];
            acc0[0][0] += hA.x * w0.x; acc0[0][1] += hA.x * w0.y; acc0[0][2] += hA.x * w0.z; acc0[0][3] += hA.x * w0.w;
            acc0[1][0] += hA.y * w0.x; acc0[1][1] += hA.y * w0.y; acc0[1][2] += hA.y * w0.z; acc0[1][3] += hA.y * w0.w;
            acc0[2][0] += hA.z * w0.x; acc0[2][1] += hA.z * w0.y; acc0[2][2] += hA.z * w0.z; acc0[2][3] += hA.z * w0.w;
            acc0[3][0] += hA.w * w0.x; acc0[3][1] += hA.w * w0.y; acc0[3][2] += hA.w * w0.z; acc0[3][3] += hA.w * w0.w;
            acc0[4][0] += hB.x * w0.x; acc0[4][1] += hB.x * w0.y; acc0[4][2] += hB.x * w0.z; acc0[4][3] += hB.x * w0.w;
            acc0[5][0] += hB.y * w0.x; acc0[5][1] += hB.y * w0.y; acc0[5][2] += hB.y * w0.z; acc0[5][3] += hB.y * w0.w;
            acc0[6][0] += hB.z * w0.x; acc0[6][1] += hB.z * w0.y; acc0[6][2] += hB.z * w0.z; acc0[6][3] += hB.z * w0.w;
            acc0[7][0] += hB.w * w0.x; acc0[7][1] += hB.w * w0.y; acc0[7][2] += hB.w * w0.z; acc0[7][3] += hB.w * w0.w;
            acc1[0][0] += hA.x * wi.x; acc1[0][1] += hA.x * wi.y; acc1[0][2] += hA.x * wi.z; acc1[0][3] += hA.x * wi.w;
            acc1[1][0] += hA.y * wi.x; acc1[1][1] += hA.y * wi.y; acc1[1][2] += hA.y * wi.z; acc1[1][3] += hA.y * wi.w;
            acc1[2][0] += hA.z * wi.x; acc1[2][1] += hA.z * wi.y; acc1[2][2] += hA.z * wi.z; acc1[2][3] += hA.z * wi.w;
            acc1[3][0] += hA.w * wi.x; acc1[3][1] += hA.w * wi.y; acc1[3][2] += hA.w * wi.z; acc1[3][3] += hA.w * wi.w;
            acc1[4][0] += hB.x * wi.x; acc1[4][1] += hB.x * wi.y; acc1[4][2] += hB.x * wi.z; acc1[4][3] += hB.x * wi.w;
            acc1[5][0] += hB.y * wi.x; acc1[5][1] += hB.y * wi.y; acc1[5][2] += hB.y * wi.z; acc1[5][3] += hB.y * wi.w;
            acc1[6][0] += hB.z * wi.x; acc1[6][1] += hB.z * wi.y; acc1[6][2] += hB.z * wi.z; acc1[6][3] += hB.z * wi.w;
            acc1[7][0] += hB.w * wi.x; acc1[7][1] += hB.w * wi.y; acc1[7][2] += hB.w * wi.z; acc1[7][3] += hB.w * wi.w;
        }

        // ---- h1 half B: kk 8..15 ----
        cpasync_wait_group<2>();
        __syncthreads();
#pragma unroll
        for (int kk = 8; kk < 16; kk++) {
            const int k = kk * 32 + kseg;
            const int e = eb ^ (k & 7);
            const float4 hA = hs1[(k << 3) | e];
            const float4 hB = hs1[(k << 3) | (e ^ 1)];
            const float4 w0 = *(const float4*)&Wt0 [kk][kseg][0];
            const float4 wi = *(const float4*)&Wt1i[kk][kseg][0];
            acc0[0][0] += hA.x * w0.x; acc0[0][1] += hA.x * w0.y; acc0[0][2] += hA.x * w0.z; acc0[0][3] += hA.x * w0.w;
            acc0[1][0] += hA.y * w0.x; acc0[1][1] += hA.y * w0.y; acc0[1][2] += hA.y * w0.z; acc0[1][3] += hA.y * w0.w;
            acc0[2][0] += hA.z * w0.x; acc0[2][1] += hA.z * w0.y; acc0[2][2] += hA.z * w0.z; acc0[2][3] += hA.z * w0.w;
            acc0[3][0] += hA.w * w0.x; acc0[3][1] += hA.w * w0.y; acc0[3][2] += hA.w * w0.z; acc0[3][3] += hA.w * w0.w;
            acc0[4][0] += hB.x * w0.x; acc0[4][1] += hB.x * w0.y; acc0[4][2] += hB.x * w0.z; acc0[4][3] += hB.x * w0.w;
            acc0[5][0] += hB.y * w0.x; acc0[5][1] += hB.y * w0.y; acc0[5][2] += hB.y * w0.z; acc0[5][3] += hB.y * w0.w;
            acc0[6][0] += hB.z * w0.x; acc0[6][1] += hB.z * w0.y; acc0[6][2] += hB.z * w0.z; acc0[6][3] += hB.z * w0.w;
            acc0[7][0] += hB.w * w0.x; acc0[7][1] += hB.w * w0.y; acc0[7][2] += hB.w * w0.z; acc0[7][3] += hB.w * w0.w;
            acc1[0][0] += hA.x * wi.x; acc1[0][1] += hA.x * wi.y; acc1[0][2] += hA.x * wi.z; acc1[0][3] += hA.x * wi.w;
            acc1[1][0] += hA.y * wi.x; acc1[1][1] += hA.y * wi.y; acc1[1][2] += hA.y * wi.z; acc1[1][3] += hA.y * wi.w;
            acc1[2][0] += hA.z * wi.x; acc1[2][1] += hA.z * wi.y; acc1[2][2] += hA.z * wi.z; acc1[2][3] += hA.z * wi.w;
            acc1[3][0] += hA.w * wi.x; acc1[3][1] += hA.w * wi.y; acc1[3][2] += hA.w * wi.z; acc1[3][3] += hA.w * wi.w;
            acc1[4][0] += hB.x * wi.x; acc1[4][1] += hB.x * wi.y; acc1[4][2] += hB.x * wi.z; acc1[4][3] += hB.x * wi.w;
            acc1[5][0] += hB.y * wi.x; acc1[5][1] += hB.y * wi.y; acc1[5][2] += hB.y * wi.z; acc1[5][3] += hB.y * wi.w;
            acc1[6][0] += hB.z * wi.x; acc1[6][1] += hB.z * wi.y; acc1[6][2] += hB.z * wi.z; acc1[6][3] += hB.z * wi.w;
            acc1[7][0] += hB.w * wi.x; acc1[7][1] += hB.w * wi.y; acc1[7][2] += hB.w * wi.z; acc1[7][3] += hB.w * wi.w;
        }

        // ---- h2 half A: kk 0..7 -> acc1 (Whh1) ----
        cpasync_wait_group<1>();
        __syncthreads();
#pragma unroll
        for (int kk = 0; kk < 8; kk++) {
            const int k = kk * 32 + kseg;
            const int e = eb ^ (k & 7);
            const float4 hA = hs2[(k << 3) | e];
            const float4 hB = hs2[(k << 3) | (e ^ 1)];
            const float4 wh = *(const float4*)&Wt1h[kk][kseg][0];
            acc1[0][0] += hA.x * wh.x; acc1[0][1] += hA.x * wh.y; acc1[0][2] += hA.x * wh.z; acc1[0][3] += hA.x * wh.w;
            acc1[1][0] += hA.y * wh.x; acc1[1][1] += hA.y * wh.y; acc1[1][2] += hA.y * wh.z; acc1[1][3] += hA.y * wh.w;
            acc1[2][0] += hA.z * wh.x; acc1[2][1] += hA.z * wh.y; acc1[2][2] += hA.z * wh.z; acc1[2][3] += hA.z * wh.w;
            acc1[3][0] += hA.w * wh.x; acc1[3][1] += hA.w * wh.y; acc1[3][2] += hA.w * wh.z; acc1[3][3] += hA.w * wh.w;
            acc1[4][0] += hB.x * wh.x; acc1[4][1] += hB.x * wh.y; acc1[4][2] += hB.x * wh.z; acc1[4][3] += hB.x * wh.w;
            acc1[5][0] += hB.y * wh.x; acc1[5][1] += hB.y * wh.y; acc1[5][2] += hB.y * wh.z; acc1[5][3] += hB.y * wh.w;
            acc1[6][0] += hB.z * wh.x; acc1[6][1] += hB.z * wh.y; acc1[6][2] += hB.z * wh.z; acc1[6][3] += hB.z * wh.w;
            acc1[7][0] += hB.w * wh.x; acc1[7][1] += hB.w * wh.y; acc1[7][2] += hB.w * wh.z; acc1[7][3] += hB.w * wh.w;
        }

        // ---- h2 half B: kk 8..15 ----
        cpasync_wait_group<0>();
        __syncthreads();
#pragma unroll
        for (int kk = 8; kk < 16; kk++) {
            const int k = kk * 32 + kseg;
            const int e = eb ^ (k & 7);
            const float4 hA = hs2[(k << 3) | e];
            const float4 hB = hs2[(k << 3) | (e ^ 1)];
            const float4 wh = *(const float4*)&Wt1h[kk][kseg][0];
            acc1[0][0] += hA.x * wh.x; acc1[0][1] += hA.x * wh.y; acc1[0][2] += hA.x * wh.z; acc1[0][3] += hA.x * wh.w;
            acc1[1][0] += hA.y * wh.x; acc1[1][1] += hA.y * wh.y; acc1[1][2] += hA.y * wh.z; acc1[1][3] += hA.y * wh.w;
            acc1[2][0] += hA.z * wh.x; acc1[2][1] += hA.z * wh.y; acc1[2][2] += hA.z * wh.z; acc1[2][3] += hA.z * wh.w;
            acc1[3][0] += hA.w * wh.x; acc1[3][1] += hA.w * wh.y; acc1[3][2] += hA.w * wh.z; acc1[3][3] += hA.w * wh.w;
            acc1[4][0] += hB.x * wh.x; acc1[4][1] += hB.x * wh.y; acc1[4][2] += hB.x * wh.z; acc1[4][3] += hB.x * wh.w;
            acc1[5][0] += hB.y * wh.x; acc1[5][1] += hB.y * wh.y; acc1[5][2] += hB.y * wh.z; acc1[5][3] += hB.y * wh.w;
            acc1[6][0] += hB.z * wh.x; acc1[6][1] += hB.z * wh.y; acc1[6][2] += hB.z * wh.z; acc1[6][3] += hB.z * wh.w;
            acc1[7][0] += hB.w * wh.x; acc1[7][1] += hB.w * wh.y; acc1[7][2] += hB.w * wh.z; acc1[7][3] += hB.w * wh.w;
        }

        // ---- dump both partial sets, one sync, both reduces ----
#pragma unroll
        for (int bi = 0; bi < 8; bi++) {
            *(float4*)&ps0[kseg * 132 + (bg * 8 + bi) * 4] =
                make_float4(acc0[bi][0], acc0[bi][1], acc0[bi][2], acc0[bi][3]);
            *(float4*)&ps1[kseg * 132 + (bg * 8 + bi) * 4] =
                make_float4(acc1[bi][0], acc1[bi][1], acc1[bi][2], acc1[bi][3]);
        }
        __syncthreads();

        {
            float a0 = 0.f, a1 = 0.f, a2 = 0.f, a3 = 0.f;
            float c0 = 0.f, c1 = 0.f, c2 = 0.f, c3 = 0.f;
#pragma unroll
            for (int ss = 0; ss < 32; ss += 4) {
                a0 += ps0[(ss + 0) * 132 + tid];
                a1 += ps0[(ss + 1) * 132 + tid];
                a2 += ps0[(ss + 2) * 132 + tid];
                a3 += ps0[(ss + 3) * 132 + tid];
                c0 += ps1[(ss + 0) * 132 + tid];
                c1 += ps1[(ss + 1) * 132 + tid];
                c2 += ps1[(ss + 2) * 132 + tid];
                c3 += ps1[(ss + 3) * 132 + tid];
            }
            if (l0) {
                const float v = tanhf(preval + (a0 + a1) + (a2 + a3));
                h1traj[(size_t)(s + 1) * HB + pre_off] = v;
            }
            if (l1) {
                const float v = tanhf(bias1v + (c0 + c1) + (c2 + c3));
                h2traj[(size_t)s * HB + pre_off] = v;
            }
        }

        // ---- grid barrier (R6-proven flat pattern) ----
        __threadfence();
        __syncthreads();

        if (tid == 0) {
            unsigned arrived = atomicAdd(&counters[s], 1u) + 1u;
            if (arrived < 128u) {
                volatile unsigned* p = &counters[s];
                while (*p < 128u) { __nanosleep(40); }
            }
        }
        __syncthreads();
    }
}

// ---------------- transpose: g_tmp [T][O][B] -> out [B][O][T] ----------------
__global__ void transpose_kernel(const float* __restrict__ tmp, float* __restrict__ out)
{
    __shared__ float s[32][33];
    const int t0 = blockIdx.x * 32;
    const int o  = blockIdx.y;
    const int tx = threadIdx.x;   // 32
    const int ty = threadIdx.y;   // 8
#pragma unroll
    for (int i = 0; i < 4; i++) {
        int tt = t0 + ty + i * 8;
        s[ty + i * 8][tx] = tmp[(size_t)tt * (OO * BB) + (size_t)o * BB + tx];
    }
    __syncthreads();
#pragma unroll
    for (int i = 0; i < 4; i++) {
        int b = ty + i * 8;
        out[(size_t)b * (OO * TT) + (size_t)o * TT + t0 + tx] = s[tx][b];
    }
}

// ---------------- launch ----------------
extern "C" void kernel_launch(void* const* d_in, const int* in_sizes, int n_in,
                              void* d_out, int out_size)
{
    const float* inputs = (const float*)d_in[0];
    const float* W_ih0  = (const float*)d_in[1];
    const float* W_hh0  = (const float*)d_in[2];
    const float* b_ih0  = (const float*)d_in[3];
    const float* b_hh0  = (const float*)d_in[4];
    const float* W_ih1  = (const float*)d_in[5];
    const float* W_hh1  = (const float*)d_in[6];
    const float* b_ih1  = (const float*)d_in[7];
    const float* b_hh1  = (const float*)d_in[8];
    const float* W_fc   = (const float*)d_in[9];
    const float* b_fc   = (const float*)d_in[10];

    float *pre, *h1, *h2, *tmp;
    unsigned* counters;
    cudaGetSymbolAddress((void**)&pre,      g_pre);
    cudaGetSymbolAddress((void**)&h1,       g_h1);
    cudaGetSymbolAddress((void**)&h2,       g_h2);
    cudaGetSymbolAddress((void**)&tmp,      g_tmp);
    cudaGetSymbolAddress((void**)&counters, g_counters);

    // opt-in to large dynamic smem (idempotent)
    cudaFuncSetAttribute(fused_rnn_kernel,
                         cudaFuncAttributeMaxDynamicSharedMemorySize, DSMEM_BYTES);

    init_kernel<<<64, 256>>>(counters, h1, h2);

    // pre0[t][j][b] = inputs[b][t][:] . W_ih0[j][:] + b_ih0[j] + b_hh0[j]
    gemm_pre_kernel<<<dim3(4, TT / 2), 256>>>(inputs, W_ih0, b_ih0, b_hh0, pre,
                                              II, (long)II, 1L, (long)TT * II, HH);

    // fused two-layer wavefront: writes h1 traj (slots 1..T) and h2 traj (slots 1..T)
    fused_rnn_kernel<<<128, 128, DSMEM_BYTES>>>(pre, h1, h2, W_hh0, W_ih1, W_hh1,
                                                b_ih1, b_hh1, counters);

    // fc: tmp[t][o][b] = h2[t][:][b] . W_fc[o][:] + b_fc[o]   (h2[t] at slot t+1)
    gemm_pre_kernel<<<dim3(1, TT / 2), 256>>>(h2 + HB, W_fc, b_fc, nullptr, tmp,
                                              HH, (long)HB, (long)BB, 1L, OO);

    // out[b][o][t] = tmp[t][o][b]
    transpose_kernel<<<dim3(16, OO), dim3(32, 8)>>>(tmp, (float*)d_out);
}

// round 17
// speedup vs baseline: 1.1347x; 1.1347x over previous
#include <cuda_runtime.h>
#include <math.h>
#include <stdint.h>

// Problem dims
#define BB 32
#define TT 512
#define II 128
#define HH 512
#define OO 128
#define HB (HH * BB)   // 16384 floats per timestep slab

// ---------------- device scratch (no allocs allowed) ----------------
__device__ float    g_pre [TT * HH * BB];          // [T][H][B] pre0
__device__ float    g_h1  [(TT + 1) * HH * BB];    // h1 traj, slot-shifted: h1[t] at slot t+1, slot0 = 0
__device__ float    g_h2  [(TT + 1) * HH * BB];    // h2 traj, slot-shifted
__device__ float    g_tmp [TT * OO * BB];          // [T][O][B] fc pre-transpose
__device__ unsigned g_counters[1024];              // per-fused-step barrier counters (513 used)

// dynamic smem: 8192 float4 (two h slabs, 128KB) + 2*32*132 floats (partials, 33KB)
#define DSMEM_BYTES (131072 + 2 * 32 * 132 * 4)

// ---------------- init: zero counters + zero slot0 each replay ----------------
__global__ void init_kernel(unsigned* counters, float* h1, float* h2) {
    int i = blockIdx.x * blockDim.x + threadIdx.x;
    int stride = gridDim.x * blockDim.x;
    for (int e = i; e < 1024; e += stride) counters[e] = 0u;
    for (int e = i; e < HB; e += stride) { h1[e] = 0.0f; h2[e] = 0.0f; }
}

// ---------------- fp32 GEMM: C[t][j][b] = bias(j) + sum_k A(t,k,b)*W[j][k] ----------------
// grid: (N/128, T/2), block: 256. Tile 128j x 64n, microtile 8j x 4n. (R4-proven)
__global__ void __launch_bounds__(256)
gemm_pre_kernel(const float* __restrict__ A, const float* __restrict__ W,
                const float* __restrict__ bias1, const float* __restrict__ bias2,
                float* __restrict__ C,
                int K, long sAt, long sAk, long sAb, int N)
{
    __shared__ float Ws[32][132];  // [k][j] padded (128 j)
    __shared__ float As[32][68];   // [k][n] padded (64 n)

    const int t0  = blockIdx.y * 2;
    const int j0  = blockIdx.x * 128;
    const int tid = threadIdx.x;
    const int jg  = tid >> 4;      // 0..15 (8 j each)
    const int ng  = tid & 15;      // 0..15 (4 n each)

    float acc[8][4];
#pragma unroll
    for (int a = 0; a < 8; a++)
#pragma unroll
        for (int b = 0; b < 4; b++) acc[a][b] = 0.0f;

    for (int kt = 0; kt < K; kt += 32) {
        __syncthreads();
        {
            const int rowb = tid >> 3;
            const int k4   = (tid & 7) * 4;
#pragma unroll
            for (int i = 0; i < 4; i++) {
                const int row = i * 32 + rowb;
                float4 v = *(const float4*)&W[(size_t)(j0 + row) * K + kt + k4];
                Ws[k4 + 0][row] = v.x;
                Ws[k4 + 1][row] = v.y;
                Ws[k4 + 2][row] = v.z;
                Ws[k4 + 3][row] = v.w;
            }
        }
        if (sAb == 1) {   // b-contiguous (trajectory layout [t][k][b])
#pragma unroll
            for (int i = 0; i < 2; i++) {
                int f = tid + i * 256;
                int k  = f >> 4;
                int nq = (f & 15) * 4;
                int tloc = nq >> 5, b4 = nq & 31;
                float4 v = *(const float4*)&A[(size_t)(t0 + tloc) * sAt +
                                              (size_t)(kt + k) * sAk + b4];
                *(float4*)&As[k][nq] = v;
            }
        } else {          // k-contiguous (inputs layout [b][t][i])
#pragma unroll
            for (int i = 0; i < 2; i++) {
                int f = tid + i * 256;
                int n  = f >> 3;
                int kq = (f & 7) * 4;
                int tloc = n >> 5, b = n & 31;
                float4 v = *(const float4*)&A[(size_t)b * sAb +
                                              (size_t)(t0 + tloc) * sAt + kt + kq];
                As[kq + 0][n] = v.x;
                As[kq + 1][n] = v.y;
                As[kq + 2][n] = v.z;
                As[kq + 3][n] = v.w;
            }
        }
        __syncthreads();
#pragma unroll
        for (int k = 0; k < 32; k++) {
            const float4 w0 = *(const float4*)&Ws[k][jg * 8];
            const float4 w1 = *(const float4*)&Ws[k][jg * 8 + 4];
            const float4 a  = *(const float4*)&As[k][ng * 4];
            acc[0][0] += w0.x * a.x; acc[0][1] += w0.x * a.y; acc[0][2] += w0.x * a.z; acc[0][3] += w0.x * a.w;
            acc[1][0] += w0.y * a.x; acc[1][1] += w0.y * a.y; acc[1][2] += w0.y * a.z; acc[1][3] += w0.y * a.w;
            acc[2][0] += w0.z * a.x; acc[2][1] += w0.z * a.y; acc[2][2] += w0.z * a.z; acc[2][3] += w0.z * a.w;
            acc[3][0] += w0.w * a.x; acc[3][1] += w0.w * a.y; acc[3][2] += w0.w * a.z; acc[3][3] += w0.w * a.w;
            acc[4][0] += w1.x * a.x; acc[4][1] += w1.x * a.y; acc[4][2] += w1.x * a.z; acc[4][3] += w1.x * a.w;
            acc[5][0] += w1.y * a.x; acc[5][1] += w1.y * a.y; acc[5][2] += w1.y * a.z; acc[5][3] += w1.y * a.w;
            acc[6][0] += w1.z * a.x; acc[6][1] += w1.z * a.y; acc[6][2] += w1.z * a.z; acc[6][3] += w1.z * a.w;
            acc[7][0] += w1.w * a.x; acc[7][1] += w1.w * a.y; acc[7][2] += w1.w * a.z; acc[7][3] += w1.w * a.w;
        }
    }

    const int tloc = ng >> 3;
    const int b4   = (ng & 7) * 4;
    float* Crow = &C[(size_t)(t0 + tloc) * N * BB + b4];
#pragma unroll
    for (int ji = 0; ji < 8; ji++) {
        int j = j0 + jg * 8 + ji;
        float bb = bias1 ? bias1[j] : 0.0f;
        if (bias2) bb += bias2[j];
        float4 o = make_float4(acc[ji][0] + bb, acc[ji][1] + bb, acc[ji][2] + bb, acc[ji][3] + bb);
        *(float4*)&Crow[(size_t)j * BB] = o;
    }
}

// ---------------- cp.async helpers ----------------
__device__ __forceinline__ void cpasync16(uint32_t saddr, const void* gaddr) {
    asm volatile("cp.async.cg.shared.global [%0], [%1], 16;" :: "r"(saddr), "l"(gaddr));
}
__device__ __forceinline__ void cpasync_commit() {
    asm volatile("cp.async.commit_group;" ::: "memory");
}
template <int N>
__device__ __forceinline__ void cpasync_wait_group() {
    asm volatile("cp.async.wait_group %0;" :: "n"(N) : "memory");
}

// ---------------- packed f32x2 helpers ----------------
union F2U { unsigned long long u; float2 f; };
__device__ __forceinline__ void pack2(F2U& d, float lo, float hi) {
    asm("mov.b64 %0, {%1, %2};" : "=l"(d.u) : "f"(lo), "f"(hi));
}
__device__ __forceinline__ void fma2(F2U& a, const F2U& x, const F2U& y) {
    asm("fma.rn.f32x2 %0, %1, %2, %0;" : "+l"(a.u) : "l"(x.u), "l"(y.u));
}

// ---------------- fused two-layer wavefront recurrence (smem-staged, FFMA2) ----------------
// grid: 128 CTAs, block: 128 threads, ~161KB dynamic smem (two h slabs + partials).
// Fused step s: stage h1[s-1] and h2[s-2] slabs via cp.async (4 commit groups,
// pipelined against the 3 GEMM slices), compute h1[s] = tanh(pre0 + W_hh0 h1)
// and h2[s-1] = tanh(bias1 + W_ih1 h1 + W_hh1 h2). Inner product uses packed
// fma.rn.f32x2 (FFMA2) to halve FMA issue. 513 barriers; R6-proven barrier.
__global__ void __launch_bounds__(128)
fused_rnn_kernel(const float* __restrict__ pre,
                 float* __restrict__ h1traj, float* __restrict__ h2traj,
                 const float* __restrict__ Whh0,
                 const float* __restrict__ Wih1, const float* __restrict__ Whh1,
                 const float* __restrict__ b_ih1, const float* __restrict__ b_hh1,
                 unsigned* counters)
{
    extern __shared__ float4 hs[];     // [0:4096) h1 slab, [4096:8192) h2 slab (swizzled), then ps0/ps1
    __shared__ float Wt0 [16][32][4];  // W_hh0 slice  8KB   (k = kk*32 + kseg)
    __shared__ float Wt1i[16][32][4];  // W_ih1 slice  8KB
    __shared__ float Wt1h[16][32][4];  // W_hh1 slice  8KB

    const int tid  = threadIdx.x;
    const int j0   = blockIdx.x * 4;
    const int bg   = tid & 3;
    const int kseg = tid >> 2;         // 0..31
    const uint32_t hs_base = (uint32_t)__cvta_generic_to_shared(hs);
    float4* const hs1 = hs;
    float4* const hs2 = hs + 4096;
    float* const ps0 = (float*)(hs + 8192);        // [32][132]
    float* const ps1 = ps0 + 32 * 132;             // [32][132]

    // preload W slices with interleaved k map: Wt[kk][ks][jj] = W[(j0+jj)*H + kk*32 + ks]
    for (int e = tid; e < 2048; e += 128) {
        int jj = e & 3;
        int ks = (e >> 2) & 31;
        int kk = e >> 7;
        size_t widx = (size_t)(j0 + jj) * HH + kk * 32 + ks;
        Wt0 [kk][ks][jj] = Whh0[widx];
        Wt1i[kk][ks][jj] = Wih1[widx];
        Wt1h[kk][ks][jj] = Whh1[widx];
    }
    __syncthreads();

    const int out_b  = tid >> 2;
    const int out_jj = tid & 3;
    const int jdx    = j0 + out_jj;
    const size_t pre_off = (size_t)jdx * BB + out_b;
    const float bias1v = b_ih1[jdx] + b_hh1[jdx];

    for (int s = 0; s <= TT; s++) {
        const bool l0 = (s < TT);                    // layer0 computes h1[s]
        const bool l1 = (s >= 1);                    // layer1 computes h2[s-1]
        const int  tp = l0 ? s : (TT - 1);           // clamped pre0 step
        const int  h2slot = l1 ? (s - 1) : 0;        // h2[s-2] slot (slot0 = zeros)

        const float4* g1 = (const float4*)(h1traj + (size_t)s * HB);
        const float4* g2 = (const float4*)(h2traj + (size_t)h2slot * HB);

        // ---- issue staging: 4 commit groups (h1 A, h1 B, h2 A, h2 B) ----
#pragma unroll
        for (int it = 0; it < 16; it++) {
            int u = tid + it * 128;
            int k = u >> 3, c = u & 7;
            int su = (k << 3) | (c ^ (k & 7));
            cpasync16(hs_base + su * 16, g1 + u);
        }
        cpasync_commit();
#pragma unroll
        for (int it = 16; it < 32; it++) {
            int u = tid + it * 128;
            int k = u >> 3, c = u & 7;
            int su = (k << 3) | (c ^ (k & 7));
            cpasync16(hs_base + su * 16, g1 + u);
        }
        cpasync_commit();
#pragma unroll
        for (int it = 0; it < 16; it++) {
            int u = tid + it * 128;
            int k = u >> 3, c = u & 7;
            int su = (k << 3) | (c ^ (k & 7));
            cpasync16(hs_base + 65536 + su * 16, g2 + u);
        }
        cpasync_commit();
#pragma unroll
        for (int it = 16; it < 32; it++) {
            int u = tid + it * 128;
            int k = u >> 3, c = u & 7;
            int su = (k << 3) | (c ^ (k & 7));
            cpasync16(hs_base + 65536 + su * 16, g2 + u);
        }
        cpasync_commit();

        const float preval = __ldcg(pre + (size_t)tp * HB + pre_off);

        // packed accumulators: [pair p over b][j], pair p covers b = b0+2p, b0+2p+1
        F2U acc0[4][4], acc1[4][4];
#pragma unroll
        for (int p = 0; p < 4; p++)
#pragma unroll
            for (int j = 0; j < 4; j++) { acc0[p][j].u = 0ull; acc1[p][j].u = 0ull; }

        const int eb = bg * 2;   // base unit col pair for this thread's 8 b

        // ---- h1 half A: kk 0..7 -> acc0 (Whh0) and acc1 (Wih1) ----
        cpasync_wait_group<3>();
        __syncthreads();
#pragma unroll
        for (int kk = 0; kk < 8; kk++) {
            const int k = kk * 32 + kseg;
            const int e = eb ^ (k & 7);
            const float4 hA = hs1[(k << 3) | e];
            const float4 hB = hs1[(k << 3) | (e ^ 1)];
            const float4 w0 = *(const float4*)&Wt0 [kk][kseg][0];
            const float4 wi = *(const float4*)&Wt1i[kk][kseg][0];
            F2U hp[4];
            pack2(hp[0], hA.x, hA.y); pack2(hp[1], hA.z, hA.w);
            pack2(hp[2], hB.x, hB.y); pack2(hp[3], hB.z, hB.w);
            F2U w0p[4], wip[4];
            pack2(w0p[0], w0.x, w0.x); pack2(w0p[1], w0.y, w0.y);
            pack2(w0p[2], w0.z, w0.z); pack2(w0p[3], w0.w, w0.w);
            pack2(wip[0], wi.x, wi.x); pack2(wip[1], wi.y, wi.y);
            pack2(wip[2], wi.z, wi.z); pack2(wip[3], wi.w, wi.w);
#pragma unroll
            for (int p = 0; p < 4; p++) {
                fma2(acc0[p][0], hp[p], w0p[0]); fma2(acc0[p][1], hp[p], w0p[1]);
                fma2(acc0[p][2], hp[p], w0p[2]); fma2(acc0[p][3], hp[p], w0p[3]);
                fma2(acc1[p][0], hp[p], wip[0]); fma2(acc1[p][1], hp[p], wip[1]);
                fma2(acc1[p][2], hp[p], wip[2]); fma2(acc1[p][3], hp[p], wip[3]);
            }
        }

        // ---- h1 half B: kk 8..15 ----
        cpasync_wait_group<2>();
        __syncthreads();
#pragma unroll
        for (int kk = 8; kk < 16; kk++) {
            const int k = kk * 32 + kseg;
            const int e = eb ^ (k & 7);
            const float4 hA = hs1[(k << 3) | e];
            const float4 hB = hs1[(k << 3) | (e ^ 1)];
            const float4 w0 = *(const float4*)&Wt0 [kk][kseg][0];
            const float4 wi = *(const float4*)&Wt1i[kk][kseg][0];
            F2U hp[4];
            pack2(hp[0], hA.x, hA.y); pack2(hp[1], hA.z, hA.w);
            pack2(hp[2], hB.x, hB.y); pack2(hp[3], hB.z, hB.w);
            F2U w0p[4], wip[4];
            pack2(w0p[0], w0.x, w0.x); pack2(w0p[1], w0.y, w0.y);
            pack2(w0p[2], w0.z, w0.z); pack2(w0p[3], w0.w, w0.w);
            pack2(wip[0], wi.x, wi.x); pack2(wip[1], wi.y, wi.y);
            pack2(wip[2], wi.z, wi.z); pack2(wip[3], wi.w, wi.w);
#pragma unroll
            for (int p = 0; p < 4; p++) {
                fma2(acc0[p][0], hp[p], w0p[0]); fma2(acc0[p][1], hp[p], w0p[1]);
                fma2(acc0[p][2], hp[p], w0p[2]); fma2(acc0[p][3], hp[p], w0p[3]);
                fma2(acc1[p][0], hp[p], wip[0]); fma2(acc1[p][1], hp[p], wip[1]);
                fma2(acc1[p][2], hp[p], wip[2]); fma2(acc1[p][3], hp[p], wip[3]);
            }
        }

        // ---- h2 half A: kk 0..7 -> acc1 (Whh1) ----
        cpasync_wait_group<1>();
        __syncthreads();
#pragma unroll
        for (int kk = 0; kk < 8; kk++) {
            const int k = kk * 32 + kseg;
            const int e = eb ^ (k & 7);
            const float4 hA = hs2[(k << 3) | e];
            const float4 hB = hs2[(k << 3) | (e ^ 1)];
            const float4 wh = *(const float4*)&Wt1h[kk][kseg][0];
            F2U hp[4];
            pack2(hp[0], hA.x, hA.y); pack2(hp[1], hA.z, hA.w);
            pack2(hp[2], hB.x, hB.y); pack2(hp[3], hB.z, hB.w);
            F2U whp[4];
            pack2(whp[0], wh.x, wh.x); pack2(whp[1], wh.y, wh.y);
            pack2(whp[2], wh.z, wh.z); pack2(whp[3], wh.w, wh.w);
#pragma unroll
            for (int p = 0; p < 4; p++) {
                fma2(acc1[p][0], hp[p], whp[0]); fma2(acc1[p][1], hp[p], whp[1]);
                fma2(acc1[p][2], hp[p], whp[2]); fma2(acc1[p][3], hp[p], whp[3]);
            }
        }

        // ---- h2 half B: kk 8..15 ----
        cpasync_wait_group<0>();
        __syncthreads();
#pragma unroll
        for (int kk = 8; kk < 16; kk++) {
            const int k = kk * 32 + kseg;
            const int e = eb ^ (k & 7);
            const float4 hA = hs2[(k << 3) | e];
            const float4 hB = hs2[(k << 3) | (e ^ 1)];
            const float4 wh = *(const float4*)&Wt1h[kk][kseg][0];
            F2U hp[4];
            pack2(hp[0], hA.x, hA.y); pack2(hp[1], hA.z, hA.w);
            pack2(hp[2], hB.x, hB.y); pack2(hp[3], hB.z, hB.w);
            F2U whp[4];
            pack2(whp[0], wh.x, wh.x); pack2(whp[1], wh.y, wh.y);
            pack2(whp[2], wh.z, wh.z); pack2(whp[3], wh.w, wh.w);
#pragma unroll
            for (int p = 0; p < 4; p++) {
                fma2(acc1[p][0], hp[p], whp[0]); fma2(acc1[p][1], hp[p], whp[1]);
                fma2(acc1[p][2], hp[p], whp[2]); fma2(acc1[p][3], hp[p], whp[3]);
            }
        }

        // ---- dump both partial sets, one sync, both reduces ----
        // pair p covers b = bg*8 + 2p (lo lane .x) and bg*8 + 2p + 1 (hi lane .y)
#pragma unroll
        for (int p = 0; p < 4; p++) {
            *(float4*)&ps0[kseg * 132 + (bg * 8 + 2 * p) * 4] =
                make_float4(acc0[p][0].f.x, acc0[p][1].f.x, acc0[p][2].f.x, acc0[p][3].f.x);
            *(float4*)&ps0[kseg * 132 + (bg * 8 + 2 * p + 1) * 4] =
                make_float4(acc0[p][0].f.y, acc0[p][1].f.y, acc0[p][2].f.y, acc0[p][3].f.y);
            *(float4*)&ps1[kseg * 132 + (bg * 8 + 2 * p) * 4] =
                make_float4(acc1[p][0].f.x, acc1[p][1].f.x, acc1[p][2].f.x, acc1[p][3].f.x);
            *(float4*)&ps1[kseg * 132 + (bg * 8 + 2 * p + 1) * 4] =
                make_float4(acc1[p][0].f.y, acc1[p][1].f.y, acc1[p][2].f.y, acc1[p][3].f.y);
        }
        __syncthreads();

        {
            float a0 = 0.f, a1 = 0.f, a2 = 0.f, a3 = 0.f;
            float c0 = 0.f, c1 = 0.f, c2 = 0.f, c3 = 0.f;
#pragma unroll
            for (int ss = 0; ss < 32; ss += 4) {
                a0 += ps0[(ss + 0) * 132 + tid];
                a1 += ps0[(ss + 1) * 132 + tid];
                a2 += ps0[(ss + 2) * 132 + tid];
                a3 += ps0[(ss + 3) * 132 + tid];
                c0 += ps1[(ss + 0) * 132 + tid];
                c1 += ps1[(ss + 1) * 132 + tid];
                c2 += ps1[(ss + 2) * 132 + tid];
                c3 += ps1[(ss + 3) * 132 + tid];
            }
            if (l0) {
                const float v = tanhf(preval + (a0 + a1) + (a2 + a3));
                h1traj[(size_t)(s + 1) * HB + pre_off] = v;
            }
            if (l1) {
                const float v = tanhf(bias1v + (c0 + c1) + (c2 + c3));
                h2traj[(size_t)s * HB + pre_off] = v;
            }
        }

        // ---- grid barrier (R6-proven flat pattern) ----
        __threadfence();
        __syncthreads();

        if (tid == 0) {
            unsigned arrived = atomicAdd(&counters[s], 1u) + 1u;
            if (arrived < 128u) {
                volatile unsigned* p = &counters[s];
                while (*p < 128u) { __nanosleep(40); }
            }
        }
        __syncthreads();
    }
}

// ---------------- transpose: g_tmp [T][O][B] -> out [B][O][T] ----------------
__global__ void transpose_kernel(const float* __restrict__ tmp, float* __restrict__ out)
{
    __shared__ float s[32][33];
    const int t0 = blockIdx.x * 32;
    const int o  = blockIdx.y;
    const int tx = threadIdx.x;   // 32
    const int ty = threadIdx.y;   // 8
#pragma unroll
    for (int i = 0; i < 4; i++) {
        int tt = t0 + ty + i * 8;
        s[ty + i * 8][tx] = tmp[(size_t)tt * (OO * BB) + (size_t)o * BB + tx];
    }
    __syncthreads();
#pragma unroll
    for (int i = 0; i < 4; i++) {
        int b = ty + i * 8;
        out[(size_t)b * (OO * TT) + (size_t)o * TT + t0 + tx] = s[tx][b];
    }
}

// ---------------- launch ----------------
extern "C" void kernel_launch(void* const* d_in, const int* in_sizes, int n_in,
                              void* d_out, int out_size)
{
    const float* inputs = (const float*)d_in[0];
    const float* W_ih0  = (const float*)d_in[1];
    const float* W_hh0  = (const float*)d_in[2];
    const float* b_ih0  = (const float*)d_in[3];
    const float* b_hh0  = (const float*)d_in[4];
    const float* W_ih1  = (const float*)d_in[5];
    const float* W_hh1  = (const float*)d_in[6];
    const float* b_ih1  = (const float*)d_in[7];
    const float* b_hh1  = (const float*)d_in[8];
    const float* W_fc   = (const float*)d_in[9];
    const float* b_fc   = (const float*)d_in[10];

    float *pre, *h1, *h2, *tmp;
    unsigned* counters;
    cudaGetSymbolAddress((void**)&pre,      g_pre);
    cudaGetSymbolAddress((void**)&h1,       g_h1);
    cudaGetSymbolAddress((void**)&h2,       g_h2);
    cudaGetSymbolAddress((void**)&tmp,      g_tmp);
    cudaGetSymbolAddress((void**)&counters, g_counters);

    // opt-in to large dynamic smem (idempotent)
    cudaFuncSetAttribute(fused_rnn_kernel,
                         cudaFuncAttributeMaxDynamicSharedMemorySize, DSMEM_BYTES);

    init_kernel<<<64, 256>>>(counters, h1, h2);

    // pre0[t][j][b] = inputs[b][t][:] . W_ih0[j][:] + b_ih0[j] + b_hh0[j]
    gemm_pre_kernel<<<dim3(4, TT / 2), 256>>>(inputs, W_ih0, b_ih0, b_hh0, pre,
                                              II, (long)II, 1L, (long)TT * II, HH);

    // fused two-layer wavefront: writes h1 traj (slots 1..T) and h2 traj (slots 1..T)
    fused_rnn_kernel<<<128, 128, DSMEM_BYTES>>>(pre, h1, h2, W_hh0, W_ih1, W_hh1,
                                                b_ih1, b_hh1, counters);

    // fc: tmp[t][o][b] = h2[t][:][b] . W_fc[o][:] + b_fc[o]   (h2[t] at slot t+1)
    gemm_pre_kernel<<<dim3(1, TT / 2), 256>>>(h2 + HB, W_fc, b_fc, nullptr, tmp,
                                              HH, (long)HB, (long)BB, 1L, OO);

    // out[b][o][t] = tmp[t][o][b]
    transpose_kernel<<<dim3(16, OO), dim3(32, 8)>>>(tmp, (float*)d_out);
}